// round 8
// baseline (speedup 1.0000x reference)
#include <cuda_runtime.h>
#include <cuda_fp16.h>
#include <cstdint>

#define H    256
#define KL   4
#define C    16
#define TPB  16         // trees per stage1 tile (M = 256 rows)

// ---------------------------------------------------------------------------
// Device scratch (no dynamic allocation allowed)
// ---------------------------------------------------------------------------
__device__ __half g_hsumh[8192 * H];         // stage1 -> stage2, fp16
__device__ __half g_Bh[KL * H * H];          // Wz  fp16, layout [k][h][d]
__device__ __half g_Wfh[H * H];              // Wzf fp16, layout [j][d]

// ---------------------------------------------------------------------------
// Stage1 SMEM layout. Padded strides (mod 128 = 16) -> conflict-free ldmatrix.
// ---------------------------------------------------------------------------
#define OFF_BIAS   0
#define OFF_A      1024
#define A_ROW_B    528
#define A_TREE_B   (16 * A_ROW_B)                  // 8448
#define A_TOTAL    (TPB * A_TREE_B)                // 135168
#define OFF_B      (OFF_A + A_TOTAL)               // 136192
#define B_ROW_B    272
#define B_SUB_B    (16 * B_ROW_B)                  // 4352  (one k-step, 128 cols)
#define B_STAGE_B  (4 * B_SUB_B)                   // 17408 (four k-steps)
#define NSTAGE     3
#define SMEM_TOTAL (OFF_B + NSTAGE * B_STAGE_B)    // 188416 -> 1 block/SM

// Stage2 SMEM layout
#define S2M        32
#define OFF2_BIAS  0
#define OFF2_A     1024
#define A2_SIZE    (S2M * A_ROW_B)                 // 16896
#define OFF2_B     (OFF2_A + A2_SIZE)              // 17920
#define B2_ROW_B   528
#define B2_STAGE   (16 * B2_ROW_B)                 // 8448
#define SMEM2      (OFF2_B + NSTAGE * B2_STAGE)    // 43264

// ---------------------------------------------------------------------------
// Helpers
// ---------------------------------------------------------------------------
__device__ __forceinline__ uint32_t smem_u32(const void* p) {
    uint32_t a;
    asm("{ .reg .u64 t; cvta.to.shared.u64 t, %1; cvt.u32.u64 %0, t; }" : "=r"(a) : "l"(p));
    return a;
}
__device__ __forceinline__ void cp16(uint32_t dst, const void* src) {
    uint64_t g;
    asm("cvta.to.global.u64 %0, %1;" : "=l"(g) : "l"(src));
    asm volatile("cp.async.cg.shared.global [%0], [%1], 16;" :: "r"(dst), "l"(g));
}
__device__ __forceinline__ void ldsm_x4(uint32_t (&r)[4], uint32_t addr) {
    asm volatile("ldmatrix.sync.aligned.m8n8.x4.shared.b16 {%0,%1,%2,%3}, [%4];"
                 : "=r"(r[0]), "=r"(r[1]), "=r"(r[2]), "=r"(r[3]) : "r"(addr));
}
__device__ __forceinline__ void ldsm_x4t(uint32_t (&r)[4], uint32_t addr) {
    asm volatile("ldmatrix.sync.aligned.m8n8.x4.trans.shared.b16 {%0,%1,%2,%3}, [%4];"
                 : "=r"(r[0]), "=r"(r[1]), "=r"(r[2]), "=r"(r[3]) : "r"(addr));
}
__device__ __forceinline__ void mma16816(float (&c)[4], const uint32_t (&a)[4],
                                         uint32_t b0, uint32_t b1) {
    asm volatile(
        "mma.sync.aligned.m16n8k16.row.col.f32.f16.f16.f32 "
        "{%0,%1,%2,%3}, {%4,%5,%6,%7}, {%8,%9}, {%0,%1,%2,%3};"
        : "+f"(c[0]), "+f"(c[1]), "+f"(c[2]), "+f"(c[3])
        : "r"(a[0]), "r"(a[1]), "r"(a[2]), "r"(a[3]), "r"(b0), "r"(b1));
}
__device__ __forceinline__ float elu(float v) { return (v > 0.0f) ? v : expm1f(v); }

// Copy one stage1 B stage: 4 k-steps = 64 h-rows x 128 cols fp16. 4 cp16/thread.
// it in 0..15: layer kl = it>>2, h-rows (it&3)*64 .. +63; cols = half*128..+127.
__device__ __forceinline__ void copyB(uint32_t dstStage, int half, int it, int tid) {
    const int kl = it >> 2;
    const int h0 = (it & 3) * 64;
    #pragma unroll
    for (int i = 0; i < 4; ++i) {
        int idx = tid + i * 256;          // 0..1023
        int r   = idx >> 4;               // 0..63
        int c8  = (idx & 15) * 8;         // 0..120 (halfs)
        const __half* src = g_Bh + (size_t)kl * 65536 + (size_t)(h0 + r) * 256
                          + half * 128 + c8;
        cp16(dstStage + r * B_ROW_B + c8 * 2, src);
    }
}

// Copy one stage2 B stage: k-step ks = 16 j-rows x 256 d-cols. 2 cp16/thread.
__device__ __forceinline__ void copyB2(uint32_t dstStage, int ks, int tid) {
    #pragma unroll
    for (int i = 0; i < 2; ++i) {
        int idx = tid + i * 256;
        int r   = idx >> 5;
        int v   = (idx & 31) * 16;
        cp16(dstStage + r * B2_ROW_B + v,
             (const char*)g_Wfh + ((size_t)(ks * 16 + r) * 512 + v));
    }
}

// ---------------------------------------------------------------------------
// Prep: Wz -> fp16 (g_Bh) and Wzf -> fp16 (g_Wfh), vectorized x4.
// ---------------------------------------------------------------------------
__global__ void prep_kernel(const float* __restrict__ Wz, const float* __restrict__ Wzf) {
    int idx = (blockIdx.x * 256 + threadIdx.x) * 4;    // < 5*65536
    bool isz = idx < KL * H * H;
    const float* src = isz ? (Wz + idx) : (Wzf + (idx - KL * H * H));
    float4 v = *(const float4*)src;
    __half2 h0 = __floats2half2_rn(v.x, v.y);
    __half2 h1 = __floats2half2_rn(v.z, v.w);
    __half* dst = isz ? (g_Bh + idx) : (g_Wfh + (idx - KL * H * H));
    *(uint2*)dst = make_uint2(*reinterpret_cast<uint32_t*>(&h0),
                              *reinterpret_cast<uint32_t*>(&h1));
}

// ---------------------------------------------------------------------------
// Stage 1 (persistent): work unit = (tile of 16 trees, N-half of 128 cols).
// Warp owns 2 trees (rows 32w..32w+31); every B fragment feeds both trees ->
// LDSM bytes per HMMA halved vs the 8-tree layout. Roll baked into A rows.
// acc covers full K (all 4 layers); ONE epilogue per unit.
// ---------------------------------------------------------------------------
__global__ __launch_bounds__(256, 1) void stage1_kernel(
    const float* __restrict__ x,
    const float* __restrict__ bz,
    const int*   __restrict__ leaf_idx,
    int nunits)
{
    extern __shared__ char smem[];
    const uint32_t sb = smem_u32(smem);
    const int tid = threadIdx.x, wid = tid >> 5, lane = tid & 31;

    // bias[d] = sum_k bz[k][d]  (persists across units)
    ((float*)(smem + OFF_BIAS))[tid] = bz[tid] + bz[H + tid] + bz[2 * H + tid] + bz[3 * H + tid];

    const uint32_t aBase0 = sb + OFF_A + (wid * 2) * A_TREE_B;   // tree 2w
    const int rowlog = lane & 15;
    const int khalf  = lane >> 4;
    const float* bias = (const float*)(smem + OFF_BIAS);

    #pragma unroll 1
    for (int u = blockIdx.x; u < nunits; u += gridDim.x) {
        const int tile = u >> 1;
        const int half = u & 1;

        __syncthreads();   // previous unit fully done before smem reuse

        // Prime first two B pipeline stages FIRST (DMA overlaps gather).
        copyB(sb + OFF_B + 0 * B_STAGE_B, half, 0, tid);
        asm volatile("cp.async.commit_group;");
        copyB(sb + OFF_B + 1 * B_STAGE_B, half, 1, tid);
        asm volatile("cp.async.commit_group;");

        // Gather A: 256 rows (16 trees x 16 children) -> fp16; 1 thread/row.
        {
            int tl = tid >> 4, child = tid & 15;
            int leaf = leaf_idx[(tile * TPB + tl) * C + child];
            const float4* src = (const float4*)(x + (size_t)leaf * H);
            char* dst = smem + OFF_A + tl * A_TREE_B + child * A_ROW_B;
            #pragma unroll
            for (int g = 0; g < 32; ++g) {
                float4 v0 = src[2 * g], v1 = src[2 * g + 1];
                __half2 h0 = __floats2half2_rn(v0.x, v0.y);
                __half2 h1 = __floats2half2_rn(v0.z, v0.w);
                __half2 h2 = __floats2half2_rn(v1.x, v1.y);
                __half2 h3 = __floats2half2_rn(v1.z, v1.w);
                *(uint4*)(dst + g * 16) = make_uint4(
                    *reinterpret_cast<uint32_t*>(&h0), *reinterpret_cast<uint32_t*>(&h1),
                    *reinterpret_cast<uint32_t*>(&h2), *reinterpret_cast<uint32_t*>(&h3));
            }
        }

        __syncthreads();   // A gather visible to all warps

        float acc0[16][4], acc1[16][4];
        #pragma unroll
        for (int nt = 0; nt < 16; ++nt)
            #pragma unroll
            for (int j = 0; j < 4; ++j) { acc0[nt][j] = 0.0f; acc1[nt][j] = 0.0f; }

        #pragma unroll 1
        for (int it = 0; it < 16; ++it) {
            if (it + 2 < 16) {
                asm volatile("cp.async.wait_group 1;");
                __syncthreads();
                copyB(sb + OFF_B + ((it + 2) % NSTAGE) * B_STAGE_B, half, it + 2, tid);
                asm volatile("cp.async.commit_group;");
            } else {
                asm volatile("cp.async.wait_group 0;");
                __syncthreads();
            }

            const uint32_t stg = sb + OFF_B + (it % NSTAGE) * B_STAGE_B;
            const int kl = it >> 2;
            const int rowp = (rowlog - kl) & 15;          // roll baked into A rows
            const uint32_t aRow0 = aBase0 + rowp * A_ROW_B + khalf * 16;
            const uint32_t aRow1 = aRow0 + A_TREE_B;

            #pragma unroll
            for (int s = 0; s < 4; ++s) {                 // four k-steps per stage
                const int ks = (it & 3) * 4 + s;

                uint32_t a0[4], a1[4];
                ldsm_x4(a0, aRow0 + ks * 32);
                ldsm_x4(a1, aRow1 + ks * 32);

                const uint32_t bb = stg + s * B_SUB_B + (lane & 15) * B_ROW_B + khalf * 16;
                uint32_t b[8][4];
                #pragma unroll
                for (int p = 0; p < 8; ++p) ldsm_x4t(b[p], bb + p * 32);
                #pragma unroll
                for (int p = 0; p < 8; ++p) {             // B frags shared by 2 trees
                    mma16816(acc0[2 * p],     a0, b[p][0], b[p][1]);
                    mma16816(acc0[2 * p + 1], a0, b[p][2], b[p][3]);
                    mma16816(acc1[2 * p],     a1, b[p][0], b[p][1]);
                    mma16816(acc1[2 * p + 1], a1, b[p][2], b[p][3]);
                }
            }
        }

        // Epilogue: +bias, ELU, 16-child reduce, store both trees' 128 cols.
        const int tree0 = tile * TPB + wid * 2;
        #pragma unroll
        for (int tt = 0; tt < 2; ++tt) {
            #pragma unroll
            for (int nt = 0; nt < 16; ++nt) {
                int col = half * 128 + nt * 8 + (lane & 3) * 2;
                float b0 = bias[col], b1 = bias[col + 1];
                float v0 = tt ? acc1[nt][0] : acc0[nt][0];
                float v1 = tt ? acc1[nt][1] : acc0[nt][1];
                float v2 = tt ? acc1[nt][2] : acc0[nt][2];
                float v3 = tt ? acc1[nt][3] : acc0[nt][3];
                float s0 = elu(v0 + b0) + elu(v2 + b0);
                float s1 = elu(v1 + b1) + elu(v3 + b1);
                #pragma unroll
                for (int sh = 4; sh <= 16; sh <<= 1) {
                    s0 += __shfl_xor_sync(0xffffffffu, s0, sh);
                    s1 += __shfl_xor_sync(0xffffffffu, s1, sh);
                }
                if (lane < 4) {
                    g_hsumh[(size_t)(tree0 + tt) * H + col]     = __float2half_rn(s0);
                    g_hsumh[(size_t)(tree0 + tt) * H + col + 1] = __float2half_rn(s1);
                }
            }
        }
    }
}

// ---------------------------------------------------------------------------
// Stage 2 (fp16 mma): out[t][:] = elu( hsum[t][:] @ Wzf + 16*bzf ).
// ---------------------------------------------------------------------------
__global__ __launch_bounds__(256) void stage2_kernel(
    const float* __restrict__ bzf,
    float*       __restrict__ out)
{
    extern __shared__ char smem[];
    const uint32_t sb = smem_u32(smem);
    const int tid = threadIdx.x, wid = tid >> 5, lane = tid & 31;
    const int blk = blockIdx.x;

    ((float*)(smem + OFF2_BIAS))[tid] = (float)C * bzf[tid];

    #pragma unroll
    for (int i = 0; i < 4; ++i) {
        int idx = tid + i * 256;
        int r = idx >> 5, v = (idx & 31) * 16;
        cp16(sb + OFF2_A + r * A_ROW_B + v,
             (const char*)g_hsumh + ((size_t)blk * S2M + r) * 512 + v);
    }
    copyB2(sb + OFF2_B + 0 * B2_STAGE, 0, tid);
    asm volatile("cp.async.commit_group;");
    copyB2(sb + OFF2_B + 1 * B2_STAGE, 1, tid);
    asm volatile("cp.async.commit_group;");

    __syncthreads();

    const int wr = wid >> 2, wc = wid & 3;
    float acc[8][4];
    #pragma unroll
    for (int nt = 0; nt < 8; ++nt)
        #pragma unroll
        for (int j = 0; j < 4; ++j) acc[nt][j] = 0.0f;

    #pragma unroll 1
    for (int ks = 0; ks < 16; ++ks) {
        if (ks + 2 < 16) {
            asm volatile("cp.async.wait_group 1;");
            __syncthreads();
            copyB2(sb + OFF2_B + ((ks + 2) % NSTAGE) * B2_STAGE, ks + 2, tid);
            asm volatile("cp.async.commit_group;");
        } else {
            asm volatile("cp.async.wait_group 0;");
            __syncthreads();
        }

        const uint32_t stg = sb + OFF2_B + (ks % NSTAGE) * B2_STAGE;

        uint32_t a[4];
        ldsm_x4(a, sb + OFF2_A + (wr * 16 + (lane & 15)) * A_ROW_B + (lane >> 4) * 16 + ks * 32);

        const uint32_t bb = stg + (lane & 15) * B2_ROW_B + (lane >> 4) * 16 + wc * 128;
        uint32_t b[4][4];
        #pragma unroll
        for (int p = 0; p < 4; ++p) ldsm_x4t(b[p], bb + p * 32);
        #pragma unroll
        for (int p = 0; p < 4; ++p) {
            mma16816(acc[2 * p],     a, b[p][0], b[p][1]);
            mma16816(acc[2 * p + 1], a, b[p][2], b[p][3]);
        }
    }

    const float* biasp = (const float*)(smem + OFF2_BIAS);
    const int row0 = blk * S2M + wr * 16 + (lane >> 2);
    #pragma unroll
    for (int nt = 0; nt < 8; ++nt) {
        int col = wc * 64 + nt * 8 + (lane & 3) * 2;
        float b0 = biasp[col], b1 = biasp[col + 1];
        float2 v0 = make_float2(elu(acc[nt][0] + b0), elu(acc[nt][1] + b1));
        float2 v1 = make_float2(elu(acc[nt][2] + b0), elu(acc[nt][3] + b1));
        *(float2*)(out + (size_t)row0 * H + col)       = v0;
        *(float2*)(out + (size_t)(row0 + 8) * H + col) = v1;
    }
}

// ---------------------------------------------------------------------------
// Launch: prep -> stage1 (persistent, M=256 tiles, N-half units) -> stage2
// ---------------------------------------------------------------------------
extern "C" void kernel_launch(void* const* d_in, const int* in_sizes, int n_in,
                              void* d_out, int out_size)
{
    const float* x        = (const float*)d_in[0];
    const float* Wz       = (const float*)d_in[1];
    const float* bz       = (const float*)d_in[2];
    const float* Wzf      = (const float*)d_in[3];
    const float* bzf      = (const float*)d_in[4];
    const int*   leaf_idx = (const int*)  d_in[5];

    const int T      = in_sizes[5] / C;        // 8192
    const int nunits = (T / TPB) * 2;          // 1024

    cudaFuncSetAttribute(stage1_kernel,
                         cudaFuncAttributeMaxDynamicSharedMemorySize, SMEM_TOTAL);
    cudaFuncSetAttribute(stage2_kernel,
                         cudaFuncAttributeMaxDynamicSharedMemorySize, SMEM2);

    prep_kernel<<<(KL * H * H + H * H) / 1024, 256>>>(Wz, Wzf);

    int grid1 = 148;
    if (grid1 > nunits) grid1 = nunits;
    stage1_kernel<<<grid1, 256, SMEM_TOTAL>>>(x, bz, leaf_idx, nunits);

    stage2_kernel<<<T / S2M, 256, SMEM2>>>(bzf, (float*)d_out);
}

// round 9
// speedup vs baseline: 1.2773x; 1.2773x over previous
#include <cuda_runtime.h>
#include <cuda_fp16.h>
#include <cstdint>

#define H    256
#define KL   4
#define C    16
#define TPB  8          // trees per stage1 tile

// ---------------------------------------------------------------------------
// Device scratch (no dynamic allocation allowed)
// ---------------------------------------------------------------------------
__device__ __half g_hsumh[8192 * H];         // stage1 -> stage2, fp16
__device__ __half g_Bh[KL * H * H];          // Wz  fp16, layout [k][h][d]
__device__ __half g_Wfh[H * H];              // Wzf fp16, layout [j][d]

// ---------------------------------------------------------------------------
// Stage1 SMEM layout. Padded strides (mod 128 = 16) -> conflict-free ldmatrix.
// ---------------------------------------------------------------------------
#define OFF_BIAS   0
#define OFF_A      1024
#define A_ROW_B    528
#define A_TREE_B   (16 * A_ROW_B)                  // 8448
#define A_TOTAL    (TPB * A_TREE_B)                // 67584
#define OFF_B      (OFF_A + A_TOTAL)               // 68608
#define B_ROW_B    272
#define B_SUB_B    (16 * B_ROW_B)                  // 4352  (one k-step, 128 cols)
#define B_STAGE_B  (2 * B_SUB_B)                   // 8704  (two k-steps)
#define NSTAGE     3
#define SMEM_TOTAL (OFF_B + NSTAGE * B_STAGE_B)    // 94720 -> 2 blocks/SM

// Stage2 SMEM layout
#define S2M        32
#define OFF2_BIAS  0
#define OFF2_A     1024
#define A2_SIZE    (S2M * A_ROW_B)                 // 16896
#define OFF2_B     (OFF2_A + A2_SIZE)              // 17920
#define B2_ROW_B   528
#define B2_STAGE   (16 * B2_ROW_B)                 // 8448
#define SMEM2      (OFF2_B + NSTAGE * B2_STAGE)    // 43264

// ---------------------------------------------------------------------------
// Helpers
// ---------------------------------------------------------------------------
__device__ __forceinline__ uint32_t smem_u32(const void* p) {
    uint32_t a;
    asm("{ .reg .u64 t; cvta.to.shared.u64 t, %1; cvt.u32.u64 %0, t; }" : "=r"(a) : "l"(p));
    return a;
}
__device__ __forceinline__ void cp16(uint32_t dst, const void* src) {
    uint64_t g;
    asm("cvta.to.global.u64 %0, %1;" : "=l"(g) : "l"(src));
    asm volatile("cp.async.cg.shared.global [%0], [%1], 16;" :: "r"(dst), "l"(g));
}
__device__ __forceinline__ void ldsm_x4(uint32_t (&r)[4], uint32_t addr) {
    asm volatile("ldmatrix.sync.aligned.m8n8.x4.shared.b16 {%0,%1,%2,%3}, [%4];"
                 : "=r"(r[0]), "=r"(r[1]), "=r"(r[2]), "=r"(r[3]) : "r"(addr));
}
__device__ __forceinline__ void ldsm_x4t(uint32_t (&r)[4], uint32_t addr) {
    asm volatile("ldmatrix.sync.aligned.m8n8.x4.trans.shared.b16 {%0,%1,%2,%3}, [%4];"
                 : "=r"(r[0]), "=r"(r[1]), "=r"(r[2]), "=r"(r[3]) : "r"(addr));
}
__device__ __forceinline__ void mma16816(float (&c)[4], const uint32_t (&a)[4],
                                         uint32_t b0, uint32_t b1) {
    asm volatile(
        "mma.sync.aligned.m16n8k16.row.col.f32.f16.f16.f32 "
        "{%0,%1,%2,%3}, {%4,%5,%6,%7}, {%8,%9}, {%0,%1,%2,%3};"
        : "+f"(c[0]), "+f"(c[1]), "+f"(c[2]), "+f"(c[3])
        : "r"(a[0]), "r"(a[1]), "r"(a[2]), "r"(a[3]), "r"(b0), "r"(b1));
}
__device__ __forceinline__ float elu(float v) { return (v > 0.0f) ? v : expm1f(v); }

// Copy one stage1 B stage: 2 k-steps = 32 h-rows x 128 cols fp16. 2 cp16/thread.
// kp in 0..31 within an nc window: kl = kp>>3, h-rows (kp&7)*32 .. +31.
__device__ __forceinline__ void copyB(uint32_t dstStage, int nc, int kp, int tid) {
    const int kl = kp >> 3;
    const int h0 = (kp & 7) * 32;
    #pragma unroll
    for (int i = 0; i < 2; ++i) {
        int idx = tid + i * 256;          // 0..511
        int r   = idx >> 4;               // 0..31 (row within the 2 k-steps)
        int c8  = (idx & 15) * 8;         // 0..120 (halfs)
        const __half* src = g_Bh + (size_t)kl * 65536 + (size_t)(h0 + r) * 256
                          + nc * 128 + c8;
        cp16(dstStage + r * B_ROW_B + c8 * 2, src);
    }
}

// Copy one stage2 B stage: k-step ks = 16 j-rows x 256 d-cols. 2 cp16/thread.
__device__ __forceinline__ void copyB2(uint32_t dstStage, int ks, int tid) {
    #pragma unroll
    for (int i = 0; i < 2; ++i) {
        int idx = tid + i * 256;
        int r   = idx >> 5;
        int v   = (idx & 31) * 16;
        cp16(dstStage + r * B2_ROW_B + v,
             (const char*)g_Wfh + ((size_t)(ks * 16 + r) * 512 + v));
    }
}

// ---------------------------------------------------------------------------
// Prep: Wz -> fp16 (g_Bh) and Wzf -> fp16 (g_Wfh), vectorized x4.
// ---------------------------------------------------------------------------
__global__ void prep_kernel(const float* __restrict__ Wz, const float* __restrict__ Wzf) {
    int idx = (blockIdx.x * 256 + threadIdx.x) * 4;    // < 5*65536
    bool isz = idx < KL * H * H;
    const float* src = isz ? (Wz + idx) : (Wzf + (idx - KL * H * H));
    float4 v = *(const float4*)src;
    __half2 h0 = __floats2half2_rn(v.x, v.y);
    __half2 h1 = __floats2half2_rn(v.z, v.w);
    __half* dst = isz ? (g_Bh + idx) : (g_Wfh + (idx - KL * H * H));
    *(uint2*)dst = make_uint2(*reinterpret_cast<uint32_t*>(&h0),
                              *reinterpret_cast<uint32_t*>(&h1));
}

// ---------------------------------------------------------------------------
// Stage 1 (persistent): block = 8 trees, warp = (tree-pair, col-group).
// Warp computes 2 trees x 64 cols; every B fragment feeds both trees ->
// LDSM/HMMA = 0.375 (vs 0.625 single-tree) while keeping 2 blocks/SM.
// Roll baked into A-row addressing. nc loops over two 128-col windows.
// ---------------------------------------------------------------------------
__global__ __launch_bounds__(256, 2) void stage1_kernel(
    const float* __restrict__ x,
    const float* __restrict__ bz,
    const int*   __restrict__ leaf_idx,
    int ntiles)
{
    extern __shared__ char smem[];
    const uint32_t sb = smem_u32(smem);
    const int tid = threadIdx.x, wid = tid >> 5, lane = tid & 31;
    const int pair = wid & 3;          // tree pair: trees 2*pair, 2*pair+1
    const int cg   = wid >> 2;         // col group within 128-col window

    // bias[d] = sum_k bz[k][d]  (persists across tiles)
    ((float*)(smem + OFF_BIAS))[tid] = bz[tid] + bz[H + tid] + bz[2 * H + tid] + bz[3 * H + tid];

    const uint32_t aBase0 = sb + OFF_A + (pair * 2) * A_TREE_B;
    const int rowlog = lane & 15;
    const int khalf  = lane >> 4;
    const float* bias = (const float*)(smem + OFF_BIAS);

    #pragma unroll 1
    for (int tile = blockIdx.x; tile < ntiles; tile += gridDim.x) {
        __syncthreads();   // previous tile fully done before smem reuse

        // Prime first two B pipeline stages FIRST (DMA overlaps gather).
        copyB(sb + OFF_B + 0 * B_STAGE_B, 0, 0, tid);
        asm volatile("cp.async.commit_group;");
        copyB(sb + OFF_B + 1 * B_STAGE_B, 0, 1, tid);
        asm volatile("cp.async.commit_group;");

        // Gather A: 128 rows (8 trees x 16 children) -> fp16; 2 threads/row.
        {
            int row = tid >> 1, half = tid & 1;
            int tree = tile * TPB + (row >> 4);
            int child = row & 15;
            int leaf = leaf_idx[tree * C + child];
            const float4* src = (const float4*)(x + (size_t)leaf * H + half * 128);
            char* dst = smem + OFF_A + (row >> 4) * A_TREE_B + child * A_ROW_B + half * 256;
            #pragma unroll
            for (int g = 0; g < 16; ++g) {
                float4 v0 = src[2 * g], v1 = src[2 * g + 1];
                __half2 h0 = __floats2half2_rn(v0.x, v0.y);
                __half2 h1 = __floats2half2_rn(v0.z, v0.w);
                __half2 h2 = __floats2half2_rn(v1.x, v1.y);
                __half2 h3 = __floats2half2_rn(v1.z, v1.w);
                *(uint4*)(dst + g * 16) = make_uint4(
                    *reinterpret_cast<uint32_t*>(&h0), *reinterpret_cast<uint32_t*>(&h1),
                    *reinterpret_cast<uint32_t*>(&h2), *reinterpret_cast<uint32_t*>(&h3));
            }
        }

        __syncthreads();   // A gather visible to all warps

        const int tree0 = tile * TPB + pair * 2;
        float acc[2][8][4];

        #pragma unroll 1
        for (int it = 0; it < 64; ++it) {
            const int nc = it >> 5, kp = it & 31, kl = kp >> 3;

            if (kp == 0) {
                #pragma unroll
                for (int tt = 0; tt < 2; ++tt)
                    #pragma unroll
                    for (int nt = 0; nt < 8; ++nt)
                        #pragma unroll
                        for (int j = 0; j < 4; ++j) acc[tt][nt][j] = 0.0f;
            }

            if (it + 2 < 64) {
                asm volatile("cp.async.wait_group 1;");
                __syncthreads();
                const int nit = it + 2;
                copyB(sb + OFF_B + (nit % NSTAGE) * B_STAGE_B, nit >> 5, nit & 31, tid);
                asm volatile("cp.async.commit_group;");
            } else {
                asm volatile("cp.async.wait_group 0;");
                __syncthreads();
            }

            const uint32_t stg = sb + OFF_B + (it % NSTAGE) * B_STAGE_B;
            const int rowp = (rowlog - kl) & 15;          // roll baked into A rows
            const uint32_t aRow0 = aBase0 + rowp * A_ROW_B + khalf * 16;

            #pragma unroll
            for (int s = 0; s < 2; ++s) {                 // two k-steps per stage
                const int ks = (kp & 7) * 2 + s;

                uint32_t a0[4], a1[4];
                ldsm_x4(a0, aRow0 + ks * 32);
                ldsm_x4(a1, aRow0 + A_TREE_B + ks * 32);

                const uint32_t bb = stg + s * B_SUB_B + (lane & 15) * B_ROW_B
                                  + khalf * 16 + cg * 128;
                uint32_t b[4][4];
                #pragma unroll
                for (int p = 0; p < 4; ++p) ldsm_x4t(b[p], bb + p * 32);
                #pragma unroll
                for (int p = 0; p < 4; ++p) {             // B shared by both trees
                    mma16816(acc[0][2 * p],     a0, b[p][0], b[p][1]);
                    mma16816(acc[0][2 * p + 1], a0, b[p][2], b[p][3]);
                    mma16816(acc[1][2 * p],     a1, b[p][0], b[p][1]);
                    mma16816(acc[1][2 * p + 1], a1, b[p][2], b[p][3]);
                }
            }

            // Epilogue at the end of each nc window: +bias, ELU, 16-child reduce.
            if (kp == 31) {
                #pragma unroll
                for (int tt = 0; tt < 2; ++tt) {
                    #pragma unroll
                    for (int nt = 0; nt < 8; ++nt) {
                        int col = nc * 128 + cg * 64 + nt * 8 + (lane & 3) * 2;
                        float b0 = bias[col], b1 = bias[col + 1];
                        float s0 = elu(acc[tt][nt][0] + b0) + elu(acc[tt][nt][2] + b0);
                        float s1 = elu(acc[tt][nt][1] + b1) + elu(acc[tt][nt][3] + b1);
                        #pragma unroll
                        for (int sh = 4; sh <= 16; sh <<= 1) {
                            s0 += __shfl_xor_sync(0xffffffffu, s0, sh);
                            s1 += __shfl_xor_sync(0xffffffffu, s1, sh);
                        }
                        if (lane < 4) {
                            g_hsumh[(size_t)(tree0 + tt) * H + col]     = __float2half_rn(s0);
                            g_hsumh[(size_t)(tree0 + tt) * H + col + 1] = __float2half_rn(s1);
                        }
                    }
                }
            }
        }
    }
}

// ---------------------------------------------------------------------------
// Stage 2 (fp16 mma): out[t][:] = elu( hsum[t][:] @ Wzf + 16*bzf ).
// ---------------------------------------------------------------------------
__global__ __launch_bounds__(256) void stage2_kernel(
    const float* __restrict__ bzf,
    float*       __restrict__ out)
{
    extern __shared__ char smem[];
    const uint32_t sb = smem_u32(smem);
    const int tid = threadIdx.x, wid = tid >> 5, lane = tid & 31;
    const int blk = blockIdx.x;

    ((float*)(smem + OFF2_BIAS))[tid] = (float)C * bzf[tid];

    #pragma unroll
    for (int i = 0; i < 4; ++i) {
        int idx = tid + i * 256;
        int r = idx >> 5, v = (idx & 31) * 16;
        cp16(sb + OFF2_A + r * A_ROW_B + v,
             (const char*)g_hsumh + ((size_t)blk * S2M + r) * 512 + v);
    }
    copyB2(sb + OFF2_B + 0 * B2_STAGE, 0, tid);
    asm volatile("cp.async.commit_group;");
    copyB2(sb + OFF2_B + 1 * B2_STAGE, 1, tid);
    asm volatile("cp.async.commit_group;");

    __syncthreads();

    const int wr = wid >> 2, wc = wid & 3;
    float acc[8][4];
    #pragma unroll
    for (int nt = 0; nt < 8; ++nt)
        #pragma unroll
        for (int j = 0; j < 4; ++j) acc[nt][j] = 0.0f;

    #pragma unroll 1
    for (int ks = 0; ks < 16; ++ks) {
        if (ks + 2 < 16) {
            asm volatile("cp.async.wait_group 1;");
            __syncthreads();
            copyB2(sb + OFF2_B + ((ks + 2) % NSTAGE) * B2_STAGE, ks + 2, tid);
            asm volatile("cp.async.commit_group;");
        } else {
            asm volatile("cp.async.wait_group 0;");
            __syncthreads();
        }

        const uint32_t stg = sb + OFF2_B + (ks % NSTAGE) * B2_STAGE;

        uint32_t a[4];
        ldsm_x4(a, sb + OFF2_A + (wr * 16 + (lane & 15)) * A_ROW_B + (lane >> 4) * 16 + ks * 32);

        const uint32_t bb = stg + (lane & 15) * B2_ROW_B + (lane >> 4) * 16 + wc * 128;
        uint32_t b[4][4];
        #pragma unroll
        for (int p = 0; p < 4; ++p) ldsm_x4t(b[p], bb + p * 32);
        #pragma unroll
        for (int p = 0; p < 4; ++p) {
            mma16816(acc[2 * p],     a, b[p][0], b[p][1]);
            mma16816(acc[2 * p + 1], a, b[p][2], b[p][3]);
        }
    }

    const float* biasp = (const float*)(smem + OFF2_BIAS);
    const int row0 = blk * S2M + wr * 16 + (lane >> 2);
    #pragma unroll
    for (int nt = 0; nt < 8; ++nt) {
        int col = wc * 64 + nt * 8 + (lane & 3) * 2;
        float b0 = biasp[col], b1 = biasp[col + 1];
        float2 v0 = make_float2(elu(acc[nt][0] + b0), elu(acc[nt][1] + b1));
        float2 v1 = make_float2(elu(acc[nt][2] + b0), elu(acc[nt][3] + b1));
        *(float2*)(out + (size_t)row0 * H + col)       = v0;
        *(float2*)(out + (size_t)(row0 + 8) * H + col) = v1;
    }
}

// ---------------------------------------------------------------------------
// Launch: prep -> stage1 (persistent, 2-trees/warp) -> stage2
// ---------------------------------------------------------------------------
extern "C" void kernel_launch(void* const* d_in, const int* in_sizes, int n_in,
                              void* d_out, int out_size)
{
    const float* x        = (const float*)d_in[0];
    const float* Wz       = (const float*)d_in[1];
    const float* bz       = (const float*)d_in[2];
    const float* Wzf      = (const float*)d_in[3];
    const float* bzf      = (const float*)d_in[4];
    const int*   leaf_idx = (const int*)  d_in[5];

    const int T      = in_sizes[5] / C;   // 8192
    const int ntiles = T / TPB;           // 1024

    cudaFuncSetAttribute(stage1_kernel,
                         cudaFuncAttributeMaxDynamicSharedMemorySize, SMEM_TOTAL);
    cudaFuncSetAttribute(stage2_kernel,
                         cudaFuncAttributeMaxDynamicSharedMemorySize, SMEM2);

    prep_kernel<<<(KL * H * H + H * H) / 1024, 256>>>(Wz, Wzf);

    int grid1 = 2 * 148;                  // 2 persistent blocks per SM
    if (grid1 > ntiles) grid1 = ntiles;
    stage1_kernel<<<grid1, 256, SMEM_TOTAL>>>(x, bz, leaf_idx, ntiles);

    stage2_kernel<<<T / S2M, 256, SMEM2>>>(bzf, (float*)d_out);
}

// round 10
// speedup vs baseline: 1.2836x; 1.0050x over previous
#include <cuda_runtime.h>
#include <cuda_fp16.h>
#include <cstdint>

#define H    256
#define KL   4
#define C    16
#define TPB  8          // trees per stage1 tile

// ---------------------------------------------------------------------------
// Device scratch (no dynamic allocation allowed)
// ---------------------------------------------------------------------------
__device__ __half g_hsumh[8192 * H];         // stage1 -> stage2, fp16
__device__ __half g_Bh[KL * H * H];          // Wz  fp16, layout [k][h][d]
__device__ __half g_Wfh[H * H];              // Wzf fp16, layout [j][d]

// Software grid barrier state (self-resetting; safe across graph replays)
__device__ volatile unsigned g_bar_count = 0;
__device__ volatile unsigned g_bar_gen   = 0;

// ---------------------------------------------------------------------------
// Stage1 SMEM layout. Padded strides (mod 128 = 16) -> conflict-free ldmatrix.
// ---------------------------------------------------------------------------
#define OFF_BIAS   0
#define OFF_A      1024
#define A_ROW_B    528
#define A_TREE_B   (16 * A_ROW_B)                  // 8448
#define A_TOTAL    (TPB * A_TREE_B)                // 67584
#define OFF_B      (OFF_A + A_TOTAL)               // 68608
#define B_ROW_B    272
#define B_SUB_B    (16 * B_ROW_B)                  // 4352  (one k-step, 128 cols)
#define B_STAGE_B  (2 * B_SUB_B)                   // 8704  (two k-steps)
#define NSTAGE     3
#define SMEM_TOTAL (OFF_B + NSTAGE * B_STAGE_B)    // 94720 -> 2 blocks/SM

// Stage2 SMEM layout (reuses the same dynamic smem after the grid barrier)
#define S2M        32
#define OFF2_BIAS  0
#define OFF2_A     1024
#define OFF2_B     (OFF2_A + S2M * A_ROW_B)        // 17920
#define B2_ROW_B   528
#define B2_STAGE   (16 * B2_ROW_B)                 // 8448

// ---------------------------------------------------------------------------
// Helpers
// ---------------------------------------------------------------------------
__device__ __forceinline__ uint32_t smem_u32(const void* p) {
    uint32_t a;
    asm("{ .reg .u64 t; cvta.to.shared.u64 t, %1; cvt.u32.u64 %0, t; }" : "=r"(a) : "l"(p));
    return a;
}
__device__ __forceinline__ void cp16(uint32_t dst, const void* src) {
    uint64_t g;
    asm("cvta.to.global.u64 %0, %1;" : "=l"(g) : "l"(src));
    asm volatile("cp.async.cg.shared.global [%0], [%1], 16;" :: "r"(dst), "l"(g));
}
__device__ __forceinline__ void ldsm_x4(uint32_t (&r)[4], uint32_t addr) {
    asm volatile("ldmatrix.sync.aligned.m8n8.x4.shared.b16 {%0,%1,%2,%3}, [%4];"
                 : "=r"(r[0]), "=r"(r[1]), "=r"(r[2]), "=r"(r[3]) : "r"(addr));
}
__device__ __forceinline__ void ldsm_x4t(uint32_t (&r)[4], uint32_t addr) {
    asm volatile("ldmatrix.sync.aligned.m8n8.x4.trans.shared.b16 {%0,%1,%2,%3}, [%4];"
                 : "=r"(r[0]), "=r"(r[1]), "=r"(r[2]), "=r"(r[3]) : "r"(addr));
}
__device__ __forceinline__ void mma16816(float (&c)[4], const uint32_t (&a)[4],
                                         uint32_t b0, uint32_t b1) {
    asm volatile(
        "mma.sync.aligned.m16n8k16.row.col.f32.f16.f16.f32 "
        "{%0,%1,%2,%3}, {%4,%5,%6,%7}, {%8,%9}, {%0,%1,%2,%3};"
        : "+f"(c[0]), "+f"(c[1]), "+f"(c[2]), "+f"(c[3])
        : "r"(a[0]), "r"(a[1]), "r"(a[2]), "r"(a[3]), "r"(b0), "r"(b1));
}
__device__ __forceinline__ float elu(float v) { return (v > 0.0f) ? v : expm1f(v); }

// Device-wide barrier. All gridDim.x blocks are co-resident by construction
// (grid == 2 * numSMs with launch_bounds(256,2)); counter self-resets so the
// kernel is replay-identical under CUDA graphs.
__device__ __forceinline__ void grid_sync(unsigned nblk) {
    __syncthreads();
    if (threadIdx.x == 0) {
        unsigned gen = g_bar_gen;
        __threadfence();
        if (atomicAdd((unsigned*)&g_bar_count, 1u) == nblk - 1) {
            g_bar_count = 0;
            __threadfence();
            g_bar_gen = gen + 1;
        } else {
            while (g_bar_gen == gen) {}
        }
    }
    __syncthreads();
}

// Copy one stage1 B stage: 2 k-steps = 32 h-rows x 128 cols fp16. 2 cp16/thread.
__device__ __forceinline__ void copyB(uint32_t dstStage, int nc, int kp, int tid) {
    const int kl = kp >> 3;
    const int h0 = (kp & 7) * 32;
    #pragma unroll
    for (int i = 0; i < 2; ++i) {
        int idx = tid + i * 256;          // 0..511
        int r   = idx >> 4;               // 0..31
        int c8  = (idx & 15) * 8;         // 0..120 (halfs)
        const __half* src = g_Bh + (size_t)kl * 65536 + (size_t)(h0 + r) * 256
                          + nc * 128 + c8;
        cp16(dstStage + r * B_ROW_B + c8 * 2, src);
    }
}

// Copy one stage2 B stage: k-step ks = 16 j-rows x 256 d-cols. 2 cp16/thread.
__device__ __forceinline__ void copyB2(uint32_t dstStage, int ks, int tid) {
    #pragma unroll
    for (int i = 0; i < 2; ++i) {
        int idx = tid + i * 256;
        int r   = idx >> 5;
        int v   = (idx & 31) * 16;
        cp16(dstStage + r * B2_ROW_B + v,
             (const char*)g_Wfh + ((size_t)(ks * 16 + r) * 512 + v));
    }
}

// ---------------------------------------------------------------------------
// Fused persistent kernel:
//   Phase 0: Wz/Wzf -> fp16 (spread over all blocks)        [grid barrier]
//   Phase 1: stage1 tiles (8 trees, warp = tree-pair x col-group, fp16 mma,
//            roll baked into A-row addressing)              [grid barrier]
//   Phase 2: stage2 GEMM + ELU -> out
// ---------------------------------------------------------------------------
__global__ __launch_bounds__(256, 2) void fused_kernel(
    const float* __restrict__ x,
    const float* __restrict__ Wz,
    const float* __restrict__ bz,
    const float* __restrict__ Wzf,
    const float* __restrict__ bzf,
    const int*   __restrict__ leaf_idx,
    float*       __restrict__ out,
    int ntiles)
{
    extern __shared__ char smem[];
    const uint32_t sb = smem_u32(smem);
    const int tid  = threadIdx.x, wid = tid >> 5, lane = tid & 31;
    const unsigned nblk = gridDim.x;

    // ---------------- Phase 0: weight conversion ----------------
    {
        const int total4 = (KL * H * H + H * H) / 4;   // 81920 float4 units
        for (int i4 = blockIdx.x * 256 + tid; i4 < total4; i4 += nblk * 256) {
            int idx = i4 * 4;
            bool isz = idx < KL * H * H;
            const float* src = isz ? (Wz + idx) : (Wzf + (idx - KL * H * H));
            float4 v = *(const float4*)src;
            __half2 h0 = __floats2half2_rn(v.x, v.y);
            __half2 h1 = __floats2half2_rn(v.z, v.w);
            __half* dst = isz ? (g_Bh + idx) : (g_Wfh + (idx - KL * H * H));
            *(uint2*)dst = make_uint2(*reinterpret_cast<uint32_t*>(&h0),
                                      *reinterpret_cast<uint32_t*>(&h1));
        }
    }
    grid_sync(nblk);

    // ---------------- Phase 1: stage1 ----------------
    const int pair = wid & 3;          // tree pair: trees 2*pair, 2*pair+1
    const int cg   = wid >> 2;         // col group within 128-col window

    ((float*)(smem + OFF_BIAS))[tid] = bz[tid] + bz[H + tid] + bz[2 * H + tid] + bz[3 * H + tid];

    const uint32_t aBase0 = sb + OFF_A + (pair * 2) * A_TREE_B;
    const int rowlog = lane & 15;
    const int khalf  = lane >> 4;
    const float* bias = (const float*)(smem + OFF_BIAS);

    #pragma unroll 1
    for (int tile = blockIdx.x; tile < ntiles; tile += nblk) {
        __syncthreads();   // previous tile fully done before smem reuse

        // Prime first two B pipeline stages FIRST (DMA overlaps gather).
        copyB(sb + OFF_B + 0 * B_STAGE_B, 0, 0, tid);
        asm volatile("cp.async.commit_group;");
        copyB(sb + OFF_B + 1 * B_STAGE_B, 0, 1, tid);
        asm volatile("cp.async.commit_group;");

        // Gather A: 128 rows (8 trees x 16 children) -> fp16; 2 threads/row.
        {
            int row = tid >> 1, half = tid & 1;
            int tree = tile * TPB + (row >> 4);
            int child = row & 15;
            int leaf = leaf_idx[tree * C + child];
            const float4* src = (const float4*)(x + (size_t)leaf * H + half * 128);
            char* dst = smem + OFF_A + (row >> 4) * A_TREE_B + child * A_ROW_B + half * 256;
            #pragma unroll
            for (int g = 0; g < 16; ++g) {
                float4 v0 = src[2 * g], v1 = src[2 * g + 1];
                __half2 h0 = __floats2half2_rn(v0.x, v0.y);
                __half2 h1 = __floats2half2_rn(v0.z, v0.w);
                __half2 h2 = __floats2half2_rn(v1.x, v1.y);
                __half2 h3 = __floats2half2_rn(v1.z, v1.w);
                *(uint4*)(dst + g * 16) = make_uint4(
                    *reinterpret_cast<uint32_t*>(&h0), *reinterpret_cast<uint32_t*>(&h1),
                    *reinterpret_cast<uint32_t*>(&h2), *reinterpret_cast<uint32_t*>(&h3));
            }
        }

        __syncthreads();   // A gather visible to all warps

        const int tree0 = tile * TPB + pair * 2;
        float acc[2][8][4];

        #pragma unroll 1
        for (int it = 0; it < 64; ++it) {
            const int nc = it >> 5, kp = it & 31, kl = kp >> 3;

            if (kp == 0) {
                #pragma unroll
                for (int tt = 0; tt < 2; ++tt)
                    #pragma unroll
                    for (int nt = 0; nt < 8; ++nt)
                        #pragma unroll
                        for (int j = 0; j < 4; ++j) acc[tt][nt][j] = 0.0f;
            }

            if (it + 2 < 64) {
                asm volatile("cp.async.wait_group 1;");
                __syncthreads();
                const int nit = it + 2;
                copyB(sb + OFF_B + (nit % NSTAGE) * B_STAGE_B, nit >> 5, nit & 31, tid);
                asm volatile("cp.async.commit_group;");
            } else {
                asm volatile("cp.async.wait_group 0;");
                __syncthreads();
            }

            const uint32_t stg = sb + OFF_B + (it % NSTAGE) * B_STAGE_B;
            const int rowp = (rowlog - kl) & 15;          // roll baked into A rows
            const uint32_t aRow0 = aBase0 + rowp * A_ROW_B + khalf * 16;

            #pragma unroll
            for (int s = 0; s < 2; ++s) {                 // two k-steps per stage
                const int ks = (kp & 7) * 2 + s;

                uint32_t a0[4], a1[4];
                ldsm_x4(a0, aRow0 + ks * 32);
                ldsm_x4(a1, aRow0 + A_TREE_B + ks * 32);

                const uint32_t bb = stg + s * B_SUB_B + (lane & 15) * B_ROW_B
                                  + khalf * 16 + cg * 128;
                uint32_t b[4][4];
                #pragma unroll
                for (int p = 0; p < 4; ++p) ldsm_x4t(b[p], bb + p * 32);
                #pragma unroll
                for (int p = 0; p < 4; ++p) {             // B shared by both trees
                    mma16816(acc[0][2 * p],     a0, b[p][0], b[p][1]);
                    mma16816(acc[0][2 * p + 1], a0, b[p][2], b[p][3]);
                    mma16816(acc[1][2 * p],     a1, b[p][0], b[p][1]);
                    mma16816(acc[1][2 * p + 1], a1, b[p][2], b[p][3]);
                }
            }

            // Epilogue at the end of each nc window: +bias, ELU, 16-child reduce.
            if (kp == 31) {
                #pragma unroll
                for (int tt = 0; tt < 2; ++tt) {
                    #pragma unroll
                    for (int nt = 0; nt < 8; ++nt) {
                        int col = nc * 128 + cg * 64 + nt * 8 + (lane & 3) * 2;
                        float b0 = bias[col], b1 = bias[col + 1];
                        float s0 = elu(acc[tt][nt][0] + b0) + elu(acc[tt][nt][2] + b0);
                        float s1 = elu(acc[tt][nt][1] + b1) + elu(acc[tt][nt][3] + b1);
                        #pragma unroll
                        for (int sh = 4; sh <= 16; sh <<= 1) {
                            s0 += __shfl_xor_sync(0xffffffffu, s0, sh);
                            s1 += __shfl_xor_sync(0xffffffffu, s1, sh);
                        }
                        if (lane < 4) {
                            g_hsumh[(size_t)(tree0 + tt) * H + col]     = __float2half_rn(s0);
                            g_hsumh[(size_t)(tree0 + tt) * H + col + 1] = __float2half_rn(s1);
                        }
                    }
                }
            }
        }
    }
    grid_sync(nblk);

    // ---------------- Phase 2: stage2 ----------------
    const int nunits2 = (ntiles * TPB) / S2M;            // 256
    #pragma unroll 1
    for (int u = blockIdx.x; u < nunits2; u += nblk) {
        __syncthreads();

        ((float*)(smem + OFF2_BIAS))[tid] = (float)C * bzf[tid];

        #pragma unroll
        for (int i = 0; i < 4; ++i) {
            int idx = tid + i * 256;
            int r = idx >> 5, v = (idx & 31) * 16;
            cp16(sb + OFF2_A + r * A_ROW_B + v,
                 (const char*)g_hsumh + ((size_t)u * S2M + r) * 512 + v);
        }
        copyB2(sb + OFF2_B + 0 * B2_STAGE, 0, tid);
        asm volatile("cp.async.commit_group;");
        copyB2(sb + OFF2_B + 1 * B2_STAGE, 1, tid);
        asm volatile("cp.async.commit_group;");

        __syncthreads();

        const int wr = wid >> 2, wc = wid & 3;
        float acc[8][4];
        #pragma unroll
        for (int nt = 0; nt < 8; ++nt)
            #pragma unroll
            for (int j = 0; j < 4; ++j) acc[nt][j] = 0.0f;

        #pragma unroll 1
        for (int ks = 0; ks < 16; ++ks) {
            if (ks + 2 < 16) {
                asm volatile("cp.async.wait_group 1;");
                __syncthreads();
                copyB2(sb + OFF2_B + ((ks + 2) % NSTAGE) * B2_STAGE, ks + 2, tid);
                asm volatile("cp.async.commit_group;");
            } else {
                asm volatile("cp.async.wait_group 0;");
                __syncthreads();
            }

            const uint32_t stg = sb + OFF2_B + (ks % NSTAGE) * B2_STAGE;

            uint32_t a[4];
            ldsm_x4(a, sb + OFF2_A + (wr * 16 + (lane & 15)) * A_ROW_B
                        + (lane >> 4) * 16 + ks * 32);

            const uint32_t bb = stg + (lane & 15) * B2_ROW_B + (lane >> 4) * 16 + wc * 128;
            uint32_t b[4][4];
            #pragma unroll
            for (int p = 0; p < 4; ++p) ldsm_x4t(b[p], bb + p * 32);
            #pragma unroll
            for (int p = 0; p < 4; ++p) {
                mma16816(acc[2 * p],     a, b[p][0], b[p][1]);
                mma16816(acc[2 * p + 1], a, b[p][2], b[p][3]);
            }
        }

        const float* biasp = (const float*)(smem + OFF2_BIAS);
        const int row0 = u * S2M + wr * 16 + (lane >> 2);
        #pragma unroll
        for (int nt = 0; nt < 8; ++nt) {
            int col = wc * 64 + nt * 8 + (lane & 3) * 2;
            float b0 = biasp[col], b1 = biasp[col + 1];
            float2 v0 = make_float2(elu(acc[nt][0] + b0), elu(acc[nt][1] + b1));
            float2 v1 = make_float2(elu(acc[nt][2] + b0), elu(acc[nt][3] + b1));
            *(float2*)(out + (size_t)row0 * H + col)       = v0;
            *(float2*)(out + (size_t)(row0 + 8) * H + col) = v1;
        }
    }
}

// ---------------------------------------------------------------------------
// Launch: ONE fused persistent kernel (grid = 2 blocks/SM, exact co-residency)
// ---------------------------------------------------------------------------
extern "C" void kernel_launch(void* const* d_in, const int* in_sizes, int n_in,
                              void* d_out, int out_size)
{
    const float* x        = (const float*)d_in[0];
    const float* Wz       = (const float*)d_in[1];
    const float* bz       = (const float*)d_in[2];
    const float* Wzf      = (const float*)d_in[3];
    const float* bzf      = (const float*)d_in[4];
    const int*   leaf_idx = (const int*)  d_in[5];

    const int T      = in_sizes[5] / C;   // 8192
    const int ntiles = T / TPB;           // 1024

    cudaFuncSetAttribute(fused_kernel,
                         cudaFuncAttributeMaxDynamicSharedMemorySize, SMEM_TOTAL);

    int dev = 0, nsm = 148;
    cudaGetDevice(&dev);
    cudaDeviceGetAttribute(&nsm, cudaDevAttrMultiProcessorCount, dev);

    int grid = 2 * nsm;                   // exactly 2 co-resident blocks per SM
    if (grid > ntiles) grid = ntiles;

    fused_kernel<<<grid, 256, SMEM_TOTAL>>>(x, Wz, bz, Wzf, bzf, leaf_idx,
                                            (float*)d_out, ntiles);
}